// round 8
// baseline (speedup 1.0000x reference)
#include <cuda_runtime.h>
#include <cuda_bf16.h>
#include <cuda_fp8.h>
#include <math.h>
#include <stdint.h>

// Problem dims (fixed)
#define T_DIM   512
#define B_DIM   64
#define IN_DIM  512
#define H_DIM   1024
#define OUT_DIM 512
#define M_DIM   (T_DIM * B_DIM)   // 32768
#define G3H     (3 * H_DIM)       // 3072

// ---------------------------------------------------------------------------
// Static device scratch
//  A-side: hi bf16 [M,K]; fp8 hi [M,K]; fp8 lo*256 [M,K]
//  B-side: hi bf16 [K,N]; fp8 hi [N,K] (transposed); fp8 lo*256 [N,K]
// ---------------------------------------------------------------------------
__device__ float         g_G [(size_t)M_DIM * G3H];
__device__ __nv_bfloat16 g_xh [(size_t)M_DIM * IN_DIM];
__device__ uint8_t       g_xh8[(size_t)M_DIM * IN_DIM];
__device__ uint8_t       g_xl8[(size_t)M_DIM * IN_DIM];
__device__ __nv_bfloat16 g_Hh [(size_t)M_DIM * H_DIM];
__device__ uint8_t       g_Hh8[(size_t)M_DIM * H_DIM];
__device__ uint8_t       g_Hl8[(size_t)M_DIM * H_DIM];
__device__ __nv_bfloat16 g_W0h [IN_DIM * G3H];
__device__ uint8_t       g_W0h8[G3H * IN_DIM], g_W0l8[G3H * IN_DIM];
__device__ __nv_bfloat16 g_W1h [H_DIM * G3H];
__device__ uint8_t       g_W1h8[G3H * H_DIM],  g_W1l8[G3H * H_DIM];
__device__ __nv_bfloat16 g_Wfh [H_DIM * OUT_DIM];
__device__ uint8_t       g_Wfh8[OUT_DIM * H_DIM], g_Wfl8[OUT_DIM * H_DIM];

// ---------------------------------------------------------------------------
// PTX helpers
// ---------------------------------------------------------------------------
__device__ __forceinline__ uint32_t smem_u32(const void* p) {
    return (uint32_t)__cvta_generic_to_shared(p);
}
__device__ __forceinline__ void cp_async16(uint32_t saddr, const void* g) {
    asm volatile("cp.async.cg.shared.global [%0], [%1], 16;\n" :: "r"(saddr), "l"(g));
}
__device__ __forceinline__ void cp_commit() {
    asm volatile("cp.async.commit_group;\n");
}
template<int N> __device__ __forceinline__ void cp_wait() {
    asm volatile("cp.async.wait_group %0;\n" :: "n"(N));
}
__device__ __forceinline__ void ldmx4(uint32_t* r, uint32_t addr) {
    asm volatile("ldmatrix.sync.aligned.m8n8.x4.shared.b16 {%0,%1,%2,%3}, [%4];\n"
                 : "=r"(r[0]), "=r"(r[1]), "=r"(r[2]), "=r"(r[3]) : "r"(addr));
}
__device__ __forceinline__ void ldmx4t(uint32_t* r, uint32_t addr) {
    asm volatile("ldmatrix.sync.aligned.m8n8.x4.trans.shared.b16 {%0,%1,%2,%3}, [%4];\n"
                 : "=r"(r[0]), "=r"(r[1]), "=r"(r[2]), "=r"(r[3]) : "r"(addr));
}
__device__ __forceinline__ void mma16816(float* d, const uint32_t* a,
                                         uint32_t b0, uint32_t b1) {
    asm volatile(
        "mma.sync.aligned.m16n8k16.row.col.f32.bf16.bf16.f32 "
        "{%0,%1,%2,%3}, {%4,%5,%6,%7}, {%8,%9}, {%0,%1,%2,%3};\n"
        : "+f"(d[0]), "+f"(d[1]), "+f"(d[2]), "+f"(d[3])
        : "r"(a[0]), "r"(a[1]), "r"(a[2]), "r"(a[3]), "r"(b0), "r"(b1));
}
__device__ __forceinline__ void mma16832f8(float* d, const uint32_t* a,
                                           uint32_t b0, uint32_t b1) {
    asm volatile(
        "mma.sync.aligned.m16n8k32.row.col.f32.e4m3.e4m3.f32 "
        "{%0,%1,%2,%3}, {%4,%5,%6,%7}, {%8,%9}, {%0,%1,%2,%3};\n"
        : "+f"(d[0]), "+f"(d[1]), "+f"(d[2]), "+f"(d[3])
        : "r"(a[0]), "r"(a[1]), "r"(a[2]), "r"(a[3]), "r"(b0), "r"(b1));
}
__device__ __forceinline__ uint8_t to_e4m3(float v) {
    return (uint8_t)__nv_cvt_float_to_fp8(v, __NV_SATFINITE, __NV_E4M3);
}

// fp8 tile swizzled offset: tile is 128 rows x 32 bytes (2 chunks of 16B/row)
__device__ __forceinline__ uint32_t f8off(int r, int chunk) {
    return (uint32_t)((r >> 2) * 128 +
                      (((r & 3) * 2 + (chunk ^ ((r >> 2) & 1))) << 4));
}

// ---------------------------------------------------------------------------
// GEMM: C = act( Ah@Bh (bf16)  +  2^-8*( Al8@Bh8 + Ah8@Bl8 ) (fp8)  + bias )
// 128x128x32 CTA tile, 8 warps (4M x 2N), 3-stage cp.async.
// actMode: 0 none; 1 gates (cols < H_DIM tanh, else sigmoid).
// ---------------------------------------------------------------------------
// stage layout: AH16 8K | BH16 8K | AH8 4K | AL8 4K | BH8 4K | BL8 4K
#define STAGE_BYTES 32768
#define OF_AH16 0
#define OF_BH16 8192
#define OF_AH8  16384
#define OF_AL8  20480
#define OF_BH8  24576
#define OF_BL8  28672
#define NSTAGE 3
#define GEMM_SMEM (NSTAGE * STAGE_BYTES)

__global__ __launch_bounds__(256, 1)
void gemm_mixed_kernel(int M, int N, int K,
                       const __nv_bfloat16* __restrict__ Ah,
                       const uint8_t* __restrict__ Ah8,
                       const uint8_t* __restrict__ Al8,
                       const __nv_bfloat16* __restrict__ Bh,
                       const uint8_t* __restrict__ Bh8,   // [N,K]
                       const uint8_t* __restrict__ Bl8,   // [N,K]
                       const float* __restrict__ bias,
                       float* __restrict__ C,
                       int actMode)
{
    extern __shared__ char smem[];
    const uint32_t sbase = smem_u32(smem);

    const int tid    = threadIdx.x;
    const int lane   = tid & 31;
    const int warpId = tid >> 5;
    const int warpM  = warpId & 3;
    const int warpN  = warpId >> 2;

    const int rowBase = blockIdx.y * 128;
    const int colBase = blockIdx.x * 128;

    float acc [2][8][4];
    float acc8[2][8][4];
    #pragma unroll
    for (int g = 0; g < 2; g++)
        #pragma unroll
        for (int n = 0; n < 8; n++)
            #pragma unroll
            for (int q = 0; q < 4; q++) { acc[g][n][q] = 0.f; acc8[g][n][q] = 0.f; }

    auto load_stage = [&](int s, int k0) {
        const uint32_t st = sbase + s * STAGE_BYTES;
        // AH16: 128 rows x 64B = 512 chunks
        #pragma unroll
        for (int i = 0; i < 2; i++) {
            const int ch  = tid + i * 256;
            const int row = ch >> 2;
            const int c   = ch & 3;
            const uint32_t soff = row * 64 + ((c ^ ((row >> 1) & 3)) << 4);
            cp_async16(st + OF_AH16 + soff,
                       Ah + (size_t)(rowBase + row) * K + k0 + c * 8);
        }
        // BH16: 32 rows x 256B = 512 chunks
        #pragma unroll
        for (int i = 0; i < 2; i++) {
            const int ch  = tid + i * 256;
            const int row = ch >> 4;
            const int c   = ch & 15;
            const uint32_t soff = row * 256 + ((c ^ (row & 7)) << 4);
            cp_async16(st + OF_BH16 + soff,
                       Bh + (size_t)(k0 + row) * N + colBase + c * 8);
        }
        // fp8 tiles: 128 rows x 32B = 256 chunks each
        {
            const int r = tid >> 1, c = tid & 1;
            const uint32_t soff = f8off(r, c);
            const size_t ga = (size_t)(rowBase + r) * K + k0 + c * 16;
            const size_t gb = (size_t)(colBase + r) * K + k0 + c * 16;
            cp_async16(st + OF_AH8 + soff, Ah8 + ga);
            cp_async16(st + OF_AL8 + soff, Al8 + ga);
            cp_async16(st + OF_BH8 + soff, Bh8 + gb);
            cp_async16(st + OF_BL8 + soff, Bl8 + gb);
        }
        cp_commit();
    };

    // fp8 ldmatrix lane addressing
    const int q8 = lane >> 3;
    const int l8 = lane & 7;

    auto compute_stage = [&](int s) {
        const uint32_t st = sbase + s * STAGE_BYTES;
        const uint32_t aH16 = st + OF_AH16;
        const uint32_t bH16 = st + OF_BH16;

        // ---- bf16 hi@hi ----
        #pragma unroll
        for (int ks = 0; ks < 2; ks++) {
            uint32_t ah[2][4];
            #pragma unroll
            for (int g = 0; g < 2; g++) {
                const int row = warpM * 32 + g * 16 + (lane & 15);
                const int cb  = ks * 2 + (lane >> 4);
                const int sc  = cb ^ ((row >> 1) & 3);
                ldmx4(ah[g], aH16 + row * 64 + sc * 16);
            }
            #pragma unroll
            for (int j = 0; j < 4; j++) {
                const int row = ks * 16 + (lane & 15);
                const int cb  = warpN * 8 + j * 2 + (lane >> 4);
                const int sc  = cb ^ (row & 7);
                uint32_t bh[4];
                ldmx4t(bh, bH16 + row * 256 + sc * 16);
                #pragma unroll
                for (int g = 0; g < 2; g++) {
                    mma16816(acc[g][2*j],   ah[g], bh[0], bh[1]);
                    mma16816(acc[g][2*j+1], ah[g], bh[2], bh[3]);
                }
            }
        }

        // ---- fp8 cross terms (k32 covers the whole stage) ----
        uint32_t a8h[2][4], a8l[2][4];
        #pragma unroll
        for (int g = 0; g < 2; g++) {
            const int wm = warpM * 32 + g * 16;
            const int r  = wm + l8 + ((q8 & 1) << 3);
            const int ck = q8 >> 1;
            const uint32_t off = f8off(r, ck);
            ldmx4(a8h[g], st + OF_AH8 + off);
            ldmx4(a8l[g], st + OF_AL8 + off);
        }
        #pragma unroll
        for (int j = 0; j < 4; j++) {
            const int n0 = warpN * 64 + j * 16;
            const int r  = n0 + l8 + ((q8 >> 1) << 3);
            const int ck = q8 & 1;
            const uint32_t off = f8off(r, ck);
            uint32_t b8h[4], b8l[4];
            ldmx4(b8h, st + OF_BH8 + off);
            ldmx4(b8l, st + OF_BL8 + off);
            #pragma unroll
            for (int g = 0; g < 2; g++) {
                mma16832f8(acc8[g][2*j],   a8l[g], b8h[0], b8h[1]);
                mma16832f8(acc8[g][2*j],   a8h[g], b8l[0], b8l[1]);
                mma16832f8(acc8[g][2*j+1], a8l[g], b8h[2], b8h[3]);
                mma16832f8(acc8[g][2*j+1], a8h[g], b8l[2], b8l[3]);
            }
        }
    };

    const int KT = K >> 5;
    load_stage(0, 0);
    load_stage(1, 32);

    for (int kt = 0; kt < KT; kt++) {
        cp_wait<1>();
        __syncthreads();
        compute_stage(kt % 3);
        if (kt + 2 < KT) load_stage((kt + 2) % 3, (kt + 2) * 32);
        else             cp_commit();
    }

    // ---- fused epilogue ----
    const int doTanh = (actMode == 1) && (colBase < H_DIM);
    const int doSig  = (actMode == 1) && (colBase >= H_DIM);
    const float INV256 = 0.00390625f;

    #pragma unroll
    for (int g = 0; g < 2; g++) {
        const int r0 = rowBase + warpM * 32 + g * 16 + (lane >> 2);
        #pragma unroll
        for (int n = 0; n < 8; n++) {
            const int col = colBase + warpN * 64 + n * 8 + (lane & 3) * 2;
            const float b0 = __ldg(bias + col);
            const float b1 = __ldg(bias + col + 1);
            float v[4];
            v[0] = acc[g][n][0] + acc8[g][n][0] * INV256 + b0;
            v[1] = acc[g][n][1] + acc8[g][n][1] * INV256 + b1;
            v[2] = acc[g][n][2] + acc8[g][n][2] * INV256 + b0;
            v[3] = acc[g][n][3] + acc8[g][n][3] * INV256 + b1;
            if (doTanh) {
                #pragma unroll
                for (int q = 0; q < 4; q++)
                    v[q] = 1.0f - __fdividef(2.0f, __expf(2.0f * v[q]) + 1.0f);
            } else if (doSig) {
                #pragma unroll
                for (int q = 0; q < 4; q++)
                    v[q] = __fdividef(1.0f, 1.0f + __expf(-v[q]));
            }
            *(float2*)(C + (size_t)r0 * N + col)       = make_float2(v[0], v[1]);
            *(float2*)(C + (size_t)(r0 + 8) * N + col) = make_float2(v[2], v[3]);
        }
    }
}

// ---------------------------------------------------------------------------
// A-side split: fp32 [M,K] -> bf16 hi [M,K], fp8 hi [M,K], fp8 lo*256 [M,K]
// 8 elements per thread.
// ---------------------------------------------------------------------------
union BF8 { __nv_bfloat16 b[8]; uint4 u; };
union B8x8 { uint8_t b[8]; uint2 u; };

__global__ void split_a_kernel(const float* __restrict__ X,
                               __nv_bfloat16* __restrict__ Xh,
                               uint8_t* __restrict__ Xh8,
                               uint8_t* __restrict__ Xl8, int n8)
{
    int i = blockIdx.x * blockDim.x + threadIdx.x;
    if (i >= n8) return;
    const float* src = X + (size_t)i * 8;
    float4 v0 = *(const float4*)src;
    float4 v1 = *(const float4*)(src + 4);
    float vv[8] = {v0.x, v0.y, v0.z, v0.w, v1.x, v1.y, v1.z, v1.w};

    BF8 hh; B8x8 h8, l8;
    #pragma unroll
    for (int j = 0; j < 8; j++) {
        __nv_bfloat16 h = __float2bfloat16(vv[j]);
        hh.b[j] = h;
        h8.b[j] = to_e4m3(vv[j]);
        l8.b[j] = to_e4m3((vv[j] - __bfloat162float(h)) * 256.0f);
    }
    *(uint4*)(Xh + (size_t)i * 8) = hh.u;
    *(uint2*)(Xh8 + (size_t)i * 8) = h8.u;
    *(uint2*)(Xl8 + (size_t)i * 8) = l8.u;
}

// ---------------------------------------------------------------------------
// Weight bf16 hi split (elementwise, [K,N] layout preserved)
// ---------------------------------------------------------------------------
__global__ void split_w_bf16(const float* __restrict__ W,
                             __nv_bfloat16* __restrict__ Wh, int n)
{
    int i = blockIdx.x * blockDim.x + threadIdx.x;
    if (i >= n) return;
    Wh[i] = __float2bfloat16(W[i]);
}

// ---------------------------------------------------------------------------
// Weight fp8 transpose split: W [K,N] -> Wh8, Wl8*256 [N,K]
// thread: (n, kg) handles 8 consecutive k.
// ---------------------------------------------------------------------------
__global__ void split_w_fp8t(const float* __restrict__ W,
                             uint8_t* __restrict__ Wh8,
                             uint8_t* __restrict__ Wl8,
                             int K, int N)
{
    const int KG = K >> 3;
    int idx = blockIdx.x * blockDim.x + threadIdx.x;
    if (idx >= KG * N) return;
    const int kg = idx / N, n = idx % N;

    B8x8 h8, l8;
    #pragma unroll
    for (int j = 0; j < 8; j++) {
        const float v = W[(size_t)(kg * 8 + j) * N + n];
        __nv_bfloat16 h = __float2bfloat16(v);
        h8.b[j] = to_e4m3(v);
        l8.b[j] = to_e4m3((v - __bfloat162float(h)) * 256.0f);
    }
    const size_t o = (size_t)n * K + kg * 8;
    *(uint2*)(Wh8 + o) = h8.u;
    *(uint2*)(Wl8 + o) = l8.u;
}

// ---------------------------------------------------------------------------
// fo-pool scan. G holds post-act gates.
//   c = fma(f, c - z, z) ;  v = o*c  -> bf16 hi + fp8 hi + fp8 lo*256
// ---------------------------------------------------------------------------
__global__ void qrnn_scan_kernel(const float* __restrict__ G,
                                 __nv_bfloat16* __restrict__ Hh,
                                 uint8_t* __restrict__ Hh8,
                                 uint8_t* __restrict__ Hl8)
{
    const int idx = blockIdx.x * blockDim.x + threadIdx.x;
    if (idx >= B_DIM * H_DIM) return;
    const int b = idx / H_DIM;
    const int h = idx % H_DIM;

    float c = 0.0f;
    #pragma unroll 4
    for (int t = 0; t < T_DIM; t++) {
        const size_t base = ((size_t)t * B_DIM + b) * G3H + h;
        const float z = G[base];
        const float f = G[base + H_DIM];
        const float o = G[base + 2 * H_DIM];
        c = fmaf(f, c - z, z);
        const float v = o * c;
        __nv_bfloat16 hi = __float2bfloat16(v);
        const size_t oidx = ((size_t)t * B_DIM + b) * H_DIM + h;
        Hh[oidx]  = hi;
        Hh8[oidx] = to_e4m3(v);
        Hl8[oidx] = to_e4m3((v - __bfloat162float(hi)) * 256.0f);
    }
}

// ---------------------------------------------------------------------------
// Launch
// ---------------------------------------------------------------------------
extern "C" void kernel_launch(void* const* d_in, const int* in_sizes, int n_in,
                              void* d_out, int out_size)
{
    const float* x   = (const float*)d_in[0];
    const float* W0  = (const float*)d_in[1];
    const float* b0  = (const float*)d_in[2];
    const float* W1  = (const float*)d_in[3];
    const float* b1  = (const float*)d_in[4];
    const float* Wfc = (const float*)d_in[5];
    const float* bfc = (const float*)d_in[6];
    float* out = (float*)d_out;

    float* G;
    __nv_bfloat16 *xh, *Hh, *W0h, *W1h, *Wfh;
    uint8_t *xh8, *xl8, *Hh8, *Hl8, *W0h8, *W0l8, *W1h8, *W1l8, *Wfh8, *Wfl8;
    cudaGetSymbolAddress((void**)&G,    g_G);
    cudaGetSymbolAddress((void**)&xh,   g_xh);
    cudaGetSymbolAddress((void**)&xh8,  g_xh8);
    cudaGetSymbolAddress((void**)&xl8,  g_xl8);
    cudaGetSymbolAddress((void**)&Hh,   g_Hh);
    cudaGetSymbolAddress((void**)&Hh8,  g_Hh8);
    cudaGetSymbolAddress((void**)&Hl8,  g_Hl8);
    cudaGetSymbolAddress((void**)&W0h,  g_W0h);
    cudaGetSymbolAddress((void**)&W0h8, g_W0h8);
    cudaGetSymbolAddress((void**)&W0l8, g_W0l8);
    cudaGetSymbolAddress((void**)&W1h,  g_W1h);
    cudaGetSymbolAddress((void**)&W1h8, g_W1h8);
    cudaGetSymbolAddress((void**)&W1l8, g_W1l8);
    cudaGetSymbolAddress((void**)&Wfh,  g_Wfh);
    cudaGetSymbolAddress((void**)&Wfh8, g_Wfh8);
    cudaGetSymbolAddress((void**)&Wfl8, g_Wfl8);

    static bool attr_done = false;
    if (!attr_done) {
        cudaFuncSetAttribute(gemm_mixed_kernel,
                             cudaFuncAttributeMaxDynamicSharedMemorySize,
                             GEMM_SMEM);
        attr_done = true;
    }

    dim3 blk(256);
    dim3 grid_g(G3H / 128, M_DIM / 128);      // 24 x 256
    dim3 grid_fc(OUT_DIM / 128, M_DIM / 128); // 4 x 256
    dim3 grid_scan((B_DIM * H_DIM + 255) / 256);

    // Splits
    { int n8 = M_DIM * IN_DIM / 8;
      split_a_kernel<<<(n8+255)/256, blk>>>(x, xh, xh8, xl8, n8); }
    { int n = IN_DIM * G3H;
      split_w_bf16<<<(n+255)/256, blk>>>(W0, W0h, n);
      int t = (IN_DIM/8) * G3H;
      split_w_fp8t<<<(t+255)/256, blk>>>(W0, W0h8, W0l8, IN_DIM, G3H); }
    { int n = H_DIM * G3H;
      split_w_bf16<<<(n+255)/256, blk>>>(W1, W1h, n);
      int t = (H_DIM/8) * G3H;
      split_w_fp8t<<<(t+255)/256, blk>>>(W1, W1h8, W1l8, H_DIM, G3H); }
    { int n = H_DIM * OUT_DIM;
      split_w_bf16<<<(n+255)/256, blk>>>(Wfc, Wfh, n);
      int t = (H_DIM/8) * OUT_DIM;
      split_w_fp8t<<<(t+255)/256, blk>>>(Wfc, Wfh8, Wfl8, H_DIM, OUT_DIM); }

    // Layer 0
    gemm_mixed_kernel<<<grid_g, blk, GEMM_SMEM>>>(M_DIM, G3H, IN_DIM,
        xh, xh8, xl8, W0h, W0h8, W0l8, b0, G, 1);
    qrnn_scan_kernel<<<grid_scan, blk>>>(G, Hh, Hh8, Hl8);

    // Layer 1
    gemm_mixed_kernel<<<grid_g, blk, GEMM_SMEM>>>(M_DIM, G3H, H_DIM,
        Hh, Hh8, Hl8, W1h, W1h8, W1l8, b1, G, 1);
    qrnn_scan_kernel<<<grid_scan, blk>>>(G, Hh, Hh8, Hl8);

    // FC head
    gemm_mixed_kernel<<<grid_fc, blk, GEMM_SMEM>>>(M_DIM, OUT_DIM, H_DIM,
        Hh, Hh8, Hl8, Wfh, Wfh8, Wfl8, bfc, out, 0);
}

// round 9
// speedup vs baseline: 1.5095x; 1.5095x over previous
#include <cuda_runtime.h>
#include <cuda_bf16.h>
#include <math.h>
#include <stdint.h>

// Problem dims (fixed)
#define T_DIM   512
#define B_DIM   64
#define IN_DIM  512
#define H_DIM   1024
#define OUT_DIM 512
#define M_DIM   (T_DIM * B_DIM)   // 32768
#define G3H     (3 * H_DIM)       // 3072

// ---------------------------------------------------------------------------
// Static device scratch
// ---------------------------------------------------------------------------
__device__ float         g_G [(size_t)M_DIM * G3H];      // post-act gates fp32
__device__ __nv_bfloat16 g_xh[(size_t)M_DIM * IN_DIM];
__device__ __nv_bfloat16 g_xl[(size_t)M_DIM * IN_DIM];
__device__ __nv_bfloat16 g_Hh[(size_t)M_DIM * H_DIM];
__device__ __nv_bfloat16 g_Hl[(size_t)M_DIM * H_DIM];
__device__ __nv_bfloat16 g_W0h[IN_DIM * G3H],  g_W0l[IN_DIM * G3H];
__device__ __nv_bfloat16 g_W1h[H_DIM * G3H],   g_W1l[H_DIM * G3H];
__device__ __nv_bfloat16 g_Wfh[H_DIM * OUT_DIM], g_Wfl[H_DIM * OUT_DIM];

// ---------------------------------------------------------------------------
// PTX helpers
// ---------------------------------------------------------------------------
__device__ __forceinline__ uint32_t smem_u32(const void* p) {
    return (uint32_t)__cvta_generic_to_shared(p);
}
__device__ __forceinline__ void cp_async16(uint32_t saddr, const void* g) {
    asm volatile("cp.async.cg.shared.global [%0], [%1], 16;\n" :: "r"(saddr), "l"(g));
}
__device__ __forceinline__ void cp_commit() {
    asm volatile("cp.async.commit_group;\n");
}
template<int N> __device__ __forceinline__ void cp_wait() {
    asm volatile("cp.async.wait_group %0;\n" :: "n"(N));
}
__device__ __forceinline__ void ldmx4(uint32_t* r, uint32_t addr) {
    asm volatile("ldmatrix.sync.aligned.m8n8.x4.shared.b16 {%0,%1,%2,%3}, [%4];\n"
                 : "=r"(r[0]), "=r"(r[1]), "=r"(r[2]), "=r"(r[3]) : "r"(addr));
}
__device__ __forceinline__ void ldmx4t(uint32_t* r, uint32_t addr) {
    asm volatile("ldmatrix.sync.aligned.m8n8.x4.trans.shared.b16 {%0,%1,%2,%3}, [%4];\n"
                 : "=r"(r[0]), "=r"(r[1]), "=r"(r[2]), "=r"(r[3]) : "r"(addr));
}
__device__ __forceinline__ void mma16816(float* d, const uint32_t* a,
                                         uint32_t b0, uint32_t b1) {
    asm volatile(
        "mma.sync.aligned.m16n8k16.row.col.f32.bf16.bf16.f32 "
        "{%0,%1,%2,%3}, {%4,%5,%6,%7}, {%8,%9}, {%0,%1,%2,%3};\n"
        : "+f"(d[0]), "+f"(d[1]), "+f"(d[2]), "+f"(d[3])
        : "r"(a[0]), "r"(a[1]), "r"(a[2]), "r"(a[3]), "r"(b0), "r"(b1));
}

// ---------------------------------------------------------------------------
// Split-precision bf16x3 GEMM with fused bias + activation epilogue.
//   C = act(Ah@Bh + Al@Bh + Ah@Bl + bias)
// 128x128x32 CTA tile, 8 warps (4M x 2N), warp tile 32x64, 3-stage cp.async.
// __launch_bounds__(256, 2): 2 CTAs/SM (192KB smem, <=128 regs) for latency
// hiding across co-resident CTAs.
// actMode: 0 = none (FC); 1 = gates (cols < H_DIM: tanh, else sigmoid).
// ---------------------------------------------------------------------------
#define STAGE_BYTES 32768     // [Ah 8K][Al 8K][Bh 8K][Bl 8K]
#define NSTAGE 3
#define GEMM_SMEM (NSTAGE * STAGE_BYTES)

__global__ __launch_bounds__(256, 2)
void gemm3_bf16_kernel(int M, int N, int K,
                       const __nv_bfloat16* __restrict__ Ah,
                       const __nv_bfloat16* __restrict__ Al,
                       const __nv_bfloat16* __restrict__ Bh,
                       const __nv_bfloat16* __restrict__ Bl,
                       const float* __restrict__ bias,
                       float* __restrict__ C,
                       int actMode)
{
    extern __shared__ char smem[];
    const uint32_t sbase = smem_u32(smem);

    const int tid    = threadIdx.x;
    const int lane   = tid & 31;
    const int warpId = tid >> 5;
    const int warpM  = warpId & 3;
    const int warpN  = warpId >> 2;

    const int rowBase = blockIdx.y * 128;
    const int colBase = blockIdx.x * 128;

    float acc[2][8][4];
    #pragma unroll
    for (int g = 0; g < 2; g++)
        #pragma unroll
        for (int n = 0; n < 8; n++)
            #pragma unroll
            for (int q = 0; q < 4; q++) acc[g][n][q] = 0.f;

    auto load_stage = [&](int s, int k0) {
        const uint32_t st = sbase + s * STAGE_BYTES;
        #pragma unroll
        for (int i = 0; i < 2; i++) {
            const int ch  = tid + i * 256;
            const int row = ch >> 2;
            const int c   = ch & 3;
            const uint32_t soff = row * 64 + ((c ^ ((row >> 1) & 3)) << 4);
            const size_t goff = (size_t)(rowBase + row) * K + k0 + c * 8;
            cp_async16(st + soff,          Ah + goff);
            cp_async16(st + 8192 + soff,   Al + goff);
        }
        #pragma unroll
        for (int i = 0; i < 2; i++) {
            const int ch  = tid + i * 256;
            const int row = ch >> 4;
            const int c   = ch & 15;
            const uint32_t soff = row * 256 + ((c ^ (row & 7)) << 4);
            const size_t goff = (size_t)(k0 + row) * N + colBase + c * 8;
            cp_async16(st + 16384 + soff,  Bh + goff);
            cp_async16(st + 24576 + soff,  Bl + goff);
        }
        cp_commit();
    };

    auto compute_stage = [&](int s) {
        const uint32_t aH = sbase + s * STAGE_BYTES;
        const uint32_t aL = aH + 8192;
        const uint32_t bH = aH + 16384;
        const uint32_t bL = aH + 24576;

        #pragma unroll
        for (int ks = 0; ks < 2; ks++) {
            uint32_t ah[2][4], al[2][4];
            #pragma unroll
            for (int g = 0; g < 2; g++) {
                const int row = warpM * 32 + g * 16 + (lane & 15);
                const int cb  = ks * 2 + (lane >> 4);
                const int sc  = cb ^ ((row >> 1) & 3);
                const uint32_t off = row * 64 + sc * 16;
                ldmx4(ah[g], aH + off);
                ldmx4(al[g], aL + off);
            }
            #pragma unroll
            for (int j = 0; j < 4; j++) {
                const int row = ks * 16 + (lane & 15);
                const int cb  = warpN * 8 + j * 2 + (lane >> 4);
                const int sc  = cb ^ (row & 7);
                const uint32_t off = row * 256 + sc * 16;
                uint32_t bh[4], bl[4];
                ldmx4t(bh, bH + off);
                ldmx4t(bl, bL + off);
                #pragma unroll
                for (int g = 0; g < 2; g++) {
                    mma16816(acc[g][2*j],   ah[g], bh[0], bh[1]);
                    mma16816(acc[g][2*j],   al[g], bh[0], bh[1]);
                    mma16816(acc[g][2*j],   ah[g], bl[0], bl[1]);
                    mma16816(acc[g][2*j+1], ah[g], bh[2], bh[3]);
                    mma16816(acc[g][2*j+1], al[g], bh[2], bh[3]);
                    mma16816(acc[g][2*j+1], ah[g], bl[2], bl[3]);
                }
            }
        }
    };

    const int KT = K >> 5;   // >= 16 always
    load_stage(0, 0);
    load_stage(1, 32);

    for (int kt = 0; kt < KT; kt++) {
        cp_wait<1>();
        __syncthreads();
        compute_stage(kt % 3);
        if (kt + 2 < KT) load_stage((kt + 2) % 3, (kt + 2) * 32);
        else             cp_commit();      // empty group keeps counting uniform
    }

    // ---- fused epilogue: +bias, activation, store ----
    const int doTanh = (actMode == 1) && (colBase < H_DIM);
    const int doSig  = (actMode == 1) && (colBase >= H_DIM);

    #pragma unroll
    for (int g = 0; g < 2; g++) {
        const int r0 = rowBase + warpM * 32 + g * 16 + (lane >> 2);
        #pragma unroll
        for (int n = 0; n < 8; n++) {
            const int col = colBase + warpN * 64 + n * 8 + (lane & 3) * 2;
            const float b0 = __ldg(bias + col);
            const float b1 = __ldg(bias + col + 1);
            float v[4] = { acc[g][n][0] + b0, acc[g][n][1] + b1,
                           acc[g][n][2] + b0, acc[g][n][3] + b1 };
            if (doTanh) {
                #pragma unroll
                for (int q = 0; q < 4; q++)
                    v[q] = 1.0f - __fdividef(2.0f, __expf(2.0f * v[q]) + 1.0f);
            } else if (doSig) {
                #pragma unroll
                for (int q = 0; q < 4; q++)
                    v[q] = __fdividef(1.0f, 1.0f + __expf(-v[q]));
            }
            *(float2*)(C + (size_t)r0 * N + col)       = make_float2(v[0], v[1]);
            *(float2*)(C + (size_t)(r0 + 8) * N + col) = make_float2(v[2], v[3]);
        }
    }
}

// ---------------------------------------------------------------------------
// fp32 -> bf16 hi/lo split (row-major)
// ---------------------------------------------------------------------------
__global__ void split_kernel(const float* __restrict__ X,
                             __nv_bfloat16* __restrict__ Xh,
                             __nv_bfloat16* __restrict__ Xl, int n)
{
    int i = blockIdx.x * blockDim.x + threadIdx.x;
    if (i >= n) return;
    float v = X[i];
    __nv_bfloat16 h = __float2bfloat16(v);
    Xh[i] = h;
    Xl[i] = __float2bfloat16(v - __bfloat162float(h));
}

// ---------------------------------------------------------------------------
// fo-pool scan. G holds post-act gates: z'=tanh(z), f'=sigmoid(f), o'=sigmoid(o)
//   c = f'*c + (1-f')*z' = fma(f', c - z', z') ;  v = o'*c -> bf16 hi/lo
// ---------------------------------------------------------------------------
__global__ void qrnn_scan_kernel(const float* __restrict__ G,
                                 __nv_bfloat16* __restrict__ Hh,
                                 __nv_bfloat16* __restrict__ Hl)
{
    const int idx = blockIdx.x * blockDim.x + threadIdx.x;
    if (idx >= B_DIM * H_DIM) return;
    const int b = idx / H_DIM;
    const int h = idx % H_DIM;

    float c = 0.0f;
    #pragma unroll 4
    for (int t = 0; t < T_DIM; t++) {
        const size_t base = ((size_t)t * B_DIM + b) * G3H + h;
        const float z = G[base];
        const float f = G[base + H_DIM];
        const float o = G[base + 2 * H_DIM];
        c = fmaf(f, c - z, z);
        const float v = o * c;
        __nv_bfloat16 hi = __float2bfloat16(v);
        const size_t oidx = ((size_t)t * B_DIM + b) * H_DIM + h;
        Hh[oidx] = hi;
        Hl[oidx] = __float2bfloat16(v - __bfloat162float(hi));
    }
}

// ---------------------------------------------------------------------------
// Launch
// ---------------------------------------------------------------------------
extern "C" void kernel_launch(void* const* d_in, const int* in_sizes, int n_in,
                              void* d_out, int out_size)
{
    const float* x   = (const float*)d_in[0];
    const float* W0  = (const float*)d_in[1];
    const float* b0  = (const float*)d_in[2];
    const float* W1  = (const float*)d_in[3];
    const float* b1  = (const float*)d_in[4];
    const float* Wfc = (const float*)d_in[5];
    const float* bfc = (const float*)d_in[6];
    float* out = (float*)d_out;

    float *G;
    __nv_bfloat16 *xh, *xl, *Hh, *Hl, *W0h, *W0l, *W1h, *W1l, *Wfh, *Wfl;
    cudaGetSymbolAddress((void**)&G,   g_G);
    cudaGetSymbolAddress((void**)&xh,  g_xh);
    cudaGetSymbolAddress((void**)&xl,  g_xl);
    cudaGetSymbolAddress((void**)&Hh,  g_Hh);
    cudaGetSymbolAddress((void**)&Hl,  g_Hl);
    cudaGetSymbolAddress((void**)&W0h, g_W0h);
    cudaGetSymbolAddress((void**)&W0l, g_W0l);
    cudaGetSymbolAddress((void**)&W1h, g_W1h);
    cudaGetSymbolAddress((void**)&W1l, g_W1l);
    cudaGetSymbolAddress((void**)&Wfh, g_Wfh);
    cudaGetSymbolAddress((void**)&Wfl, g_Wfl);

    static bool attr_done = false;
    if (!attr_done) {
        cudaFuncSetAttribute(gemm3_bf16_kernel,
                             cudaFuncAttributeMaxDynamicSharedMemorySize,
                             GEMM_SMEM);
        attr_done = true;
    }

    dim3 blk(256);
    dim3 grid_g(G3H / 128, M_DIM / 128);      // 24 x 256
    dim3 grid_fc(OUT_DIM / 128, M_DIM / 128); // 4 x 256
    dim3 grid_scan((B_DIM * H_DIM + 255) / 256);

    // Splits
    {
        int n;
        n = M_DIM * IN_DIM;   split_kernel<<<(n+255)/256, blk>>>(x,   xh,  xl,  n);
        n = IN_DIM * G3H;     split_kernel<<<(n+255)/256, blk>>>(W0,  W0h, W0l, n);
        n = H_DIM * G3H;      split_kernel<<<(n+255)/256, blk>>>(W1,  W1h, W1l, n);
        n = H_DIM * OUT_DIM;  split_kernel<<<(n+255)/256, blk>>>(Wfc, Wfh, Wfl, n);
    }

    // Layer 0: GEMM (+fused act) -> scan
    gemm3_bf16_kernel<<<grid_g, blk, GEMM_SMEM>>>(M_DIM, G3H, IN_DIM,
                                                  xh, xl, W0h, W0l, b0, G, 1);
    qrnn_scan_kernel<<<grid_scan, blk>>>(G, Hh, Hl);

    // Layer 1
    gemm3_bf16_kernel<<<grid_g, blk, GEMM_SMEM>>>(M_DIM, G3H, H_DIM,
                                                  Hh, Hl, W1h, W1l, b1, G, 1);
    qrnn_scan_kernel<<<grid_scan, blk>>>(G, Hh, Hl);

    // FC head (no act)
    gemm3_bf16_kernel<<<grid_fc, blk, GEMM_SMEM>>>(M_DIM, OUT_DIM, H_DIM,
                                                   Hh, Hl, Wfh, Wfl, bfc, out, 0);
}

// round 10
// speedup vs baseline: 2.0308x; 1.3454x over previous
#include <cuda_runtime.h>
#include <cuda_fp16.h>
#include <math.h>
#include <stdint.h>

// Problem dims (fixed)
#define T_DIM   512
#define B_DIM   64
#define IN_DIM  512
#define H_DIM   1024
#define OUT_DIM 512
#define M_DIM   (T_DIM * B_DIM)   // 32768
#define G3H     (3 * H_DIM)       // 3072

// ---------------------------------------------------------------------------
// Static device scratch
//  A-side (activations): fp16 hi + fp16 lo   (full fp32 precision recovered)
//  B-side (weights):     fp16 only           (dropped term ~2^-12)
// ---------------------------------------------------------------------------
__device__ float  g_G [(size_t)M_DIM * G3H];      // post-act gates fp32
__device__ __half g_xh[(size_t)M_DIM * IN_DIM];
__device__ __half g_xl[(size_t)M_DIM * IN_DIM];
__device__ __half g_Hh[(size_t)M_DIM * H_DIM];
__device__ __half g_Hl[(size_t)M_DIM * H_DIM];
__device__ __half g_W0h[IN_DIM * G3H];
__device__ __half g_W1h[H_DIM * G3H];
__device__ __half g_Wfh[H_DIM * OUT_DIM];

// ---------------------------------------------------------------------------
// PTX helpers
// ---------------------------------------------------------------------------
__device__ __forceinline__ uint32_t smem_u32(const void* p) {
    return (uint32_t)__cvta_generic_to_shared(p);
}
__device__ __forceinline__ void cp_async16(uint32_t saddr, const void* g) {
    asm volatile("cp.async.cg.shared.global [%0], [%1], 16;\n" :: "r"(saddr), "l"(g));
}
__device__ __forceinline__ void cp_commit() {
    asm volatile("cp.async.commit_group;\n");
}
template<int N> __device__ __forceinline__ void cp_wait() {
    asm volatile("cp.async.wait_group %0;\n" :: "n"(N));
}
__device__ __forceinline__ void ldmx4(uint32_t* r, uint32_t addr) {
    asm volatile("ldmatrix.sync.aligned.m8n8.x4.shared.b16 {%0,%1,%2,%3}, [%4];\n"
                 : "=r"(r[0]), "=r"(r[1]), "=r"(r[2]), "=r"(r[3]) : "r"(addr));
}
__device__ __forceinline__ void ldmx4t(uint32_t* r, uint32_t addr) {
    asm volatile("ldmatrix.sync.aligned.m8n8.x4.trans.shared.b16 {%0,%1,%2,%3}, [%4];\n"
                 : "=r"(r[0]), "=r"(r[1]), "=r"(r[2]), "=r"(r[3]) : "r"(addr));
}
__device__ __forceinline__ void mma16816h(float* d, const uint32_t* a,
                                          uint32_t b0, uint32_t b1) {
    asm volatile(
        "mma.sync.aligned.m16n8k16.row.col.f32.f16.f16.f32 "
        "{%0,%1,%2,%3}, {%4,%5,%6,%7}, {%8,%9}, {%0,%1,%2,%3};\n"
        : "+f"(d[0]), "+f"(d[1]), "+f"(d[2]), "+f"(d[3])
        : "r"(a[0]), "r"(a[1]), "r"(a[2]), "r"(a[3]), "r"(b0), "r"(b1));
}

// ---------------------------------------------------------------------------
// fp16x2 split GEMM with fused bias + activation epilogue.
//   C = act( Ah@Bh + Al@Bh + bias )      (= A@Bh exactly, B fp16-truncated)
// 128x128x32 CTA tile, 8 warps (4M x 2N), warp tile 32x64, 3-stage cp.async,
// 2 CTAs/SM. actMode: 0 none (FC); 1 gates (cols < H_DIM tanh, else sigmoid).
// ---------------------------------------------------------------------------
#define STAGE_BYTES 24576     // [Ah 8K][Al 8K][Bh 8K]
#define NSTAGE 3
#define GEMM_SMEM (NSTAGE * STAGE_BYTES)

__global__ __launch_bounds__(256, 2)
void gemm2_f16_kernel(int M, int N, int K,
                      const __half* __restrict__ Ah,
                      const __half* __restrict__ Al,
                      const __half* __restrict__ Bh,
                      const float* __restrict__ bias,
                      float* __restrict__ C,
                      int actMode)
{
    extern __shared__ char smem[];
    const uint32_t sbase = smem_u32(smem);

    const int tid    = threadIdx.x;
    const int lane   = tid & 31;
    const int warpId = tid >> 5;
    const int warpM  = warpId & 3;
    const int warpN  = warpId >> 2;

    const int rowBase = blockIdx.y * 128;
    const int colBase = blockIdx.x * 128;

    float acc[2][8][4];
    #pragma unroll
    for (int g = 0; g < 2; g++)
        #pragma unroll
        for (int n = 0; n < 8; n++)
            #pragma unroll
            for (int q = 0; q < 4; q++) acc[g][n][q] = 0.f;

    auto load_stage = [&](int s, int k0) {
        const uint32_t st = sbase + s * STAGE_BYTES;
        // A tiles (hi, lo): 128 rows x 64B = 512 chunks each
        #pragma unroll
        for (int i = 0; i < 2; i++) {
            const int ch  = tid + i * 256;
            const int row = ch >> 2;
            const int c   = ch & 3;
            const uint32_t soff = row * 64 + ((c ^ ((row >> 1) & 3)) << 4);
            const size_t goff = (size_t)(rowBase + row) * K + k0 + c * 8;
            cp_async16(st + soff,        Ah + goff);
            cp_async16(st + 8192 + soff, Al + goff);
        }
        // B tile: 32 rows x 256B = 512 chunks
        #pragma unroll
        for (int i = 0; i < 2; i++) {
            const int ch  = tid + i * 256;
            const int row = ch >> 4;
            const int c   = ch & 15;
            const uint32_t soff = row * 256 + ((c ^ (row & 7)) << 4);
            const size_t goff = (size_t)(k0 + row) * N + colBase + c * 8;
            cp_async16(st + 16384 + soff, Bh + goff);
        }
        cp_commit();
    };

    auto compute_stage = [&](int s) {
        const uint32_t aH = sbase + s * STAGE_BYTES;
        const uint32_t aL = aH + 8192;
        const uint32_t bH = aH + 16384;

        #pragma unroll
        for (int ks = 0; ks < 2; ks++) {
            uint32_t ah[2][4], al[2][4];
            #pragma unroll
            for (int g = 0; g < 2; g++) {
                const int row = warpM * 32 + g * 16 + (lane & 15);
                const int cb  = ks * 2 + (lane >> 4);
                const int sc  = cb ^ ((row >> 1) & 3);
                const uint32_t off = row * 64 + sc * 16;
                ldmx4(ah[g], aH + off);
                ldmx4(al[g], aL + off);
            }
            #pragma unroll
            for (int j = 0; j < 4; j++) {
                const int row = ks * 16 + (lane & 15);
                const int cb  = warpN * 8 + j * 2 + (lane >> 4);
                const int sc  = cb ^ (row & 7);
                const uint32_t off = row * 256 + sc * 16;
                uint32_t bh[4];
                ldmx4t(bh, bH + off);
                #pragma unroll
                for (int g = 0; g < 2; g++) {
                    mma16816h(acc[g][2*j],   ah[g], bh[0], bh[1]);
                    mma16816h(acc[g][2*j],   al[g], bh[0], bh[1]);
                    mma16816h(acc[g][2*j+1], ah[g], bh[2], bh[3]);
                    mma16816h(acc[g][2*j+1], al[g], bh[2], bh[3]);
                }
            }
        }
    };

    const int KT = K >> 5;
    load_stage(0, 0);
    load_stage(1, 32);

    for (int kt = 0; kt < KT; kt++) {
        cp_wait<1>();
        __syncthreads();
        compute_stage(kt % 3);
        if (kt + 2 < KT) load_stage((kt + 2) % 3, (kt + 2) * 32);
        else             cp_commit();      // empty group keeps counting uniform
    }

    // ---- fused epilogue: +bias, activation, store ----
    const int doTanh = (actMode == 1) && (colBase < H_DIM);
    const int doSig  = (actMode == 1) && (colBase >= H_DIM);

    #pragma unroll
    for (int g = 0; g < 2; g++) {
        const int r0 = rowBase + warpM * 32 + g * 16 + (lane >> 2);
        #pragma unroll
        for (int n = 0; n < 8; n++) {
            const int col = colBase + warpN * 64 + n * 8 + (lane & 3) * 2;
            const float b0 = __ldg(bias + col);
            const float b1 = __ldg(bias + col + 1);
            float v[4] = { acc[g][n][0] + b0, acc[g][n][1] + b1,
                           acc[g][n][2] + b0, acc[g][n][3] + b1 };
            if (doTanh) {
                #pragma unroll
                for (int q = 0; q < 4; q++)
                    v[q] = 1.0f - __fdividef(2.0f, __expf(2.0f * v[q]) + 1.0f);
            } else if (doSig) {
                #pragma unroll
                for (int q = 0; q < 4; q++)
                    v[q] = __fdividef(1.0f, 1.0f + __expf(-v[q]));
            }
            *(float2*)(C + (size_t)r0 * N + col)       = make_float2(v[0], v[1]);
            *(float2*)(C + (size_t)(r0 + 8) * N + col) = make_float2(v[2], v[3]);
        }
    }
}

// ---------------------------------------------------------------------------
// fp32 -> fp16 hi/lo split (A-side: x)
// ---------------------------------------------------------------------------
__global__ void split_a_kernel(const float* __restrict__ X,
                               __half* __restrict__ Xh,
                               __half* __restrict__ Xl, int n)
{
    int i = blockIdx.x * blockDim.x + threadIdx.x;
    if (i >= n) return;
    float v = X[i];
    __half h = __float2half(v);
    Xh[i] = h;
    Xl[i] = __float2half(v - __half2float(h));
}

// ---------------------------------------------------------------------------
// fp32 -> fp16 (weights, hi only)
// ---------------------------------------------------------------------------
__global__ void cvt_w_kernel(const float* __restrict__ W,
                             __half* __restrict__ Wh, int n)
{
    int i = blockIdx.x * blockDim.x + threadIdx.x;
    if (i >= n) return;
    Wh[i] = __float2half(W[i]);
}

// ---------------------------------------------------------------------------
// fo-pool scan. G holds post-act gates: z'=tanh(z), f'=sigmoid(f), o'=sigmoid(o)
//   c = fma(f', c - z', z') ;  v = o'*c -> fp16 hi/lo
// ---------------------------------------------------------------------------
__global__ void qrnn_scan_kernel(const float* __restrict__ G,
                                 __half* __restrict__ Hh,
                                 __half* __restrict__ Hl)
{
    const int idx = blockIdx.x * blockDim.x + threadIdx.x;
    if (idx >= B_DIM * H_DIM) return;
    const int b = idx / H_DIM;
    const int h = idx % H_DIM;

    float c = 0.0f;
    #pragma unroll 4
    for (int t = 0; t < T_DIM; t++) {
        const size_t base = ((size_t)t * B_DIM + b) * G3H + h;
        const float z = G[base];
        const float f = G[base + H_DIM];
        const float o = G[base + 2 * H_DIM];
        c = fmaf(f, c - z, z);
        const float v = o * c;
        __half hi = __float2half(v);
        const size_t oidx = ((size_t)t * B_DIM + b) * H_DIM + h;
        Hh[oidx] = hi;
        Hl[oidx] = __float2half(v - __half2float(hi));
    }
}

// ---------------------------------------------------------------------------
// Launch
// ---------------------------------------------------------------------------
extern "C" void kernel_launch(void* const* d_in, const int* in_sizes, int n_in,
                              void* d_out, int out_size)
{
    const float* x   = (const float*)d_in[0];
    const float* W0  = (const float*)d_in[1];
    const float* b0  = (const float*)d_in[2];
    const float* W1  = (const float*)d_in[3];
    const float* b1  = (const float*)d_in[4];
    const float* Wfc = (const float*)d_in[5];
    const float* bfc = (const float*)d_in[6];
    float* out = (float*)d_out;

    float* G;
    __half *xh, *xl, *Hh, *Hl, *W0h, *W1h, *Wfh;
    cudaGetSymbolAddress((void**)&G,   g_G);
    cudaGetSymbolAddress((void**)&xh,  g_xh);
    cudaGetSymbolAddress((void**)&xl,  g_xl);
    cudaGetSymbolAddress((void**)&Hh,  g_Hh);
    cudaGetSymbolAddress((void**)&Hl,  g_Hl);
    cudaGetSymbolAddress((void**)&W0h, g_W0h);
    cudaGetSymbolAddress((void**)&W1h, g_W1h);
    cudaGetSymbolAddress((void**)&Wfh, g_Wfh);

    static bool attr_done = false;
    if (!attr_done) {
        cudaFuncSetAttribute(gemm2_f16_kernel,
                             cudaFuncAttributeMaxDynamicSharedMemorySize,
                             GEMM_SMEM);
        attr_done = true;
    }

    dim3 blk(256);
    dim3 grid_g(G3H / 128, M_DIM / 128);      // 24 x 256
    dim3 grid_fc(OUT_DIM / 128, M_DIM / 128); // 4 x 256
    dim3 grid_scan((B_DIM * H_DIM + 255) / 256);

    // Splits / conversions
    {
        int n;
        n = M_DIM * IN_DIM;   split_a_kernel<<<(n+255)/256, blk>>>(x, xh, xl, n);
        n = IN_DIM * G3H;     cvt_w_kernel<<<(n+255)/256, blk>>>(W0,  W0h, n);
        n = H_DIM * G3H;      cvt_w_kernel<<<(n+255)/256, blk>>>(W1,  W1h, n);
        n = H_DIM * OUT_DIM;  cvt_w_kernel<<<(n+255)/256, blk>>>(Wfc, Wfh, n);
    }

    // Layer 0: GEMM (+fused act) -> scan
    gemm2_f16_kernel<<<grid_g, blk, GEMM_SMEM>>>(M_DIM, G3H, IN_DIM,
                                                 xh, xl, W0h, b0, G, 1);
    qrnn_scan_kernel<<<grid_scan, blk>>>(G, Hh, Hl);

    // Layer 1
    gemm2_f16_kernel<<<grid_g, blk, GEMM_SMEM>>>(M_DIM, G3H, H_DIM,
                                                 Hh, Hl, W1h, b1, G, 1);
    qrnn_scan_kernel<<<grid_scan, blk>>>(G, Hh, Hl);

    // FC head (no act)
    gemm2_f16_kernel<<<grid_fc, blk, GEMM_SMEM>>>(M_DIM, OUT_DIM, H_DIM,
                                                  Hh, Hl, Wfh, bfc, out, 0);
}